// round 1
// baseline (speedup 1.0000x reference)
#include <cuda_runtime.h>
#include <math.h>

#define NN 50000
#define DD 256
#define NE 500000
#define NQ 200000
#define EPSV 1e-5f

// ---------------- scratch (device globals; no allocation) ----------------
__device__ float g_h[(size_t)NN * DD];     // node features / hidden
__device__ float g_m[(size_t)NN * DD];     // h @ W
__device__ float g_agg[(size_t)NN * DD];   // edge-aggregated
__device__ float g_dinv[NN];
__device__ int   g_deg[NN];
__device__ float g_stats[2 * DD];          // [sum, sumsq] per feature
__device__ float g_z[(size_t)NQ * DD];     // h[u]*h[v]
__device__ float g_t[(size_t)NQ * DD];     // relu(z@pW1+pb1)

// ---------------- utility kernels ----------------
__global__ void k_zero_f(float* __restrict__ p, int n) {
    int i = blockIdx.x * blockDim.x + threadIdx.x;
    int s = gridDim.x * blockDim.x;
    for (; i < n; i += s) p[i] = 0.f;
}
__global__ void k_zero_i(int* __restrict__ p, int n) {
    int i = blockIdx.x * blockDim.x + threadIdx.x;
    int s = gridDim.x * blockDim.x;
    for (; i < n; i += s) p[i] = 0;
}

// degree (rows only) + self loop handled in dinv
__global__ void k_deg(const int* __restrict__ adj_row) {
    int e = blockIdx.x * blockDim.x + threadIdx.x;
    if (e < NE) atomicAdd(&g_deg[adj_row[e]], 1);
}
__global__ void k_dinv() {
    int i = blockIdx.x * blockDim.x + threadIdx.x;
    if (i < NN) g_dinv[i] = rsqrtf((float)g_deg[i] + 1.0f);
}

// h = concat(emb, x) along features: emb -> cols [0,128), x -> cols [128,256)
__global__ void k_concat(const float* __restrict__ emb, const float* __restrict__ x) {
    int idx = blockIdx.x * blockDim.x + threadIdx.x;
    if (idx >= NN * DD) return;
    int i = idx >> 8, j = idx & 255;
    g_h[idx] = (j < 128) ? emb[i * 128 + j] : x[i * 128 + (j - 128)];
}

// ---------------- tiled fp32 GEMM: C[M,256] = A[M,256] @ B[256,256] ----------------
// 64x64 tile, BK=16, 256 threads, 4x4 microtile, float4 smem accesses.
__global__ void __launch_bounds__(256) k_sgemm(const float* __restrict__ A,
                                               const float* __restrict__ B,
                                               const float* __restrict__ bias,
                                               float* __restrict__ C,
                                               int M, int do_relu) {
    __shared__ __align__(16) float As[16][64];
    __shared__ __align__(16) float Bs[16][64];
    const int tid = threadIdx.x;
    const int tx = tid & 15, ty = tid >> 4;
    const int row0 = blockIdx.y * 64;
    const int col0 = blockIdx.x * 64;
    const int a_row = tid >> 2, a_k4 = tid & 3;     // A: one float4 (4 k's) per thread
    const int b_k = tid >> 4, b_c4 = tid & 15;      // B: one float4 (4 cols) per thread
    const int ar = row0 + a_row;
    const bool a_ok = (ar < M);
    const float* Aptr = A + (size_t)ar * DD + a_k4 * 4;
    const float* Bptr = B + (size_t)b_k * DD + col0 + b_c4 * 4;

    float acc[4][4] = {};
    for (int k0 = 0; k0 < DD; k0 += 16) {
        float4 av = make_float4(0.f, 0.f, 0.f, 0.f);
        if (a_ok) av = *(const float4*)(Aptr + k0);
        As[a_k4 * 4 + 0][a_row] = av.x;
        As[a_k4 * 4 + 1][a_row] = av.y;
        As[a_k4 * 4 + 2][a_row] = av.z;
        As[a_k4 * 4 + 3][a_row] = av.w;
        *(float4*)&Bs[b_k][b_c4 * 4] = *(const float4*)(Bptr + (size_t)k0 * DD);
        __syncthreads();
#pragma unroll
        for (int k = 0; k < 16; k++) {
            float4 ra = *(const float4*)&As[k][ty * 4];
            float4 rb = *(const float4*)&Bs[k][tx * 4];
            acc[0][0] += ra.x * rb.x; acc[0][1] += ra.x * rb.y; acc[0][2] += ra.x * rb.z; acc[0][3] += ra.x * rb.w;
            acc[1][0] += ra.y * rb.x; acc[1][1] += ra.y * rb.y; acc[1][2] += ra.y * rb.z; acc[1][3] += ra.y * rb.w;
            acc[2][0] += ra.z * rb.x; acc[2][1] += ra.z * rb.y; acc[2][2] += ra.z * rb.z; acc[2][3] += ra.z * rb.w;
            acc[3][0] += ra.w * rb.x; acc[3][1] += ra.w * rb.y; acc[3][2] += ra.w * rb.z; acc[3][3] += ra.w * rb.w;
        }
        __syncthreads();
    }
#pragma unroll
    for (int i = 0; i < 4; i++) {
        int r = row0 + ty * 4 + i;
        if (r >= M) continue;
#pragma unroll
        for (int j = 0; j < 4; j++) {
            int c = col0 + tx * 4 + j;
            float v = acc[i][j];
            if (bias) v += bias[c];
            if (do_relu) v = fmaxf(v, 0.f);
            C[(size_t)r * DD + c] = v;
        }
    }
}

// ---------------- edge scatter: agg[r] += m[c] * dinv[r]*dinv[c] (one warp / edge) ----------------
__global__ void __launch_bounds__(256) k_scatter(const int* __restrict__ adj_row,
                                                 const int* __restrict__ adj_col) {
    int e = blockIdx.x * 8 + (threadIdx.x >> 5);
    if (e >= NE) return;
    int lane = threadIdx.x & 31;
    int r = adj_row[e], c = adj_col[e];
    float nrm = g_dinv[r] * g_dinv[c];
    const float4* src = (const float4*)(g_m + (size_t)c * DD);
    float* dst = g_agg + (size_t)r * DD;
#pragma unroll
    for (int i = lane; i < 64; i += 32) {
        float4 v = src[i];
        float* d = dst + i * 4;
        atomicAdd(d + 0, v.x * nrm);
        atomicAdd(d + 1, v.y * nrm);
        atomicAdd(d + 2, v.z * nrm);
        atomicAdd(d + 3, v.w * nrm);
    }
}

// out[idx] = agg[idx] + dinv[i]^2 * m[idx] + bias[j]
__global__ void k_combine(const float* __restrict__ bias, float* __restrict__ out) {
    int idx = blockIdx.x * blockDim.x + threadIdx.x;
    if (idx >= NN * DD) return;
    int i = idx >> 8, j = idx & 255;
    float di = g_dinv[i];
    out[idx] = g_agg[idx] + di * di * g_m[idx] + bias[j];
}

// per-feature sum / sumsq over nodes (coalesced: thread t handles feature t)
__global__ void __launch_bounds__(256) k_stats() {
    int j = threadIdx.x;
    int r0 = blockIdx.x * 128;
    int rend = min(r0 + 128, NN);
    float s = 0.f, sq = 0.f;
    for (int r = r0; r < rend; r++) {
        float v = g_agg[(size_t)r * DD + j];
        s += v; sq += v * v;
    }
    atomicAdd(&g_stats[j], s);
    atomicAdd(&g_stats[DD + j], sq);
}

// batchnorm (batch stats, biased var) + relu: g_h = relu(bn(g_agg))
__global__ void k_bnrelu(const float* __restrict__ gamma, const float* __restrict__ beta) {
    int idx = blockIdx.x * blockDim.x + threadIdx.x;
    if (idx >= NN * DD) return;
    int j = idx & 255;
    const float invn = 1.0f / (float)NN;
    float mean = g_stats[j] * invn;
    float var = g_stats[DD + j] * invn - mean * mean;
    float v = (g_agg[idx] - mean) * rsqrtf(var + EPSV) * gamma[j] + beta[j];
    g_h[idx] = fmaxf(v, 0.f);
}

// z[q] = h[edges[0][q]] * h[edges[1][q]]  (float4 over features)
__global__ void k_z(const int* __restrict__ edges) {
    int idx = blockIdx.x * blockDim.x + threadIdx.x; // over NQ*64 float4s
    if (idx >= NQ * 64) return;
    int q = idx >> 6, f4 = idx & 63;
    int u = edges[q], v = edges[NQ + q];
    float4 a = *(const float4*)(g_h + (size_t)u * DD + f4 * 4);
    float4 b = *(const float4*)(g_h + (size_t)v * DD + f4 * 4);
    ((float4*)g_z)[idx] = make_float4(a.x * b.x, a.y * b.y, a.z * b.z, a.w * b.w);
}

// out[q] = sigmoid(dot(t[q], pW2) + pb2)  (one warp per query)
__global__ void __launch_bounds__(256) k_final(const float* __restrict__ pW2,
                                               const float* __restrict__ pb2,
                                               float* __restrict__ out) {
    __shared__ float w[DD];
    for (int i = threadIdx.x; i < DD; i += 256) w[i] = pW2[i];
    __syncthreads();
    int q = (blockIdx.x * 256 + threadIdx.x) >> 5;
    int lane = threadIdx.x & 31;
    if (q >= NQ) return;
    const float4* t = (const float4*)(g_t + (size_t)q * DD);
    float s = 0.f;
#pragma unroll
    for (int i = lane; i < 64; i += 32) {
        float4 v = t[i];
        s += v.x * w[i * 4 + 0] + v.y * w[i * 4 + 1] + v.z * w[i * 4 + 2] + v.w * w[i * 4 + 3];
    }
#pragma unroll
    for (int o = 16; o; o >>= 1) s += __shfl_down_sync(0xffffffffu, s, o);
    if (lane == 0) out[q] = 1.f / (1.f + expf(-(s + pb2[0])));
}

// ---------------- launch ----------------
extern "C" void kernel_launch(void* const* d_in, const int* in_sizes, int n_in,
                              void* d_out, int out_size) {
    const float* x       = (const float*)d_in[0];
    const int*   adj_row = (const int*)d_in[1];
    const int*   adj_col = (const int*)d_in[2];
    const int*   edges   = (const int*)d_in[3];
    const float* emb     = (const float*)d_in[4];
    const float* W1      = (const float*)d_in[5];
    const float* b1      = (const float*)d_in[6];
    const float* W2      = (const float*)d_in[7];
    const float* b2      = (const float*)d_in[8];
    const float* gamma   = (const float*)d_in[9];
    const float* beta    = (const float*)d_in[10];
    const float* pW1     = (const float*)d_in[11];
    const float* pb1     = (const float*)d_in[12];
    const float* pW2     = (const float*)d_in[13];
    const float* pb2     = (const float*)d_in[14];
    float* out = (float*)d_out;

    float *p_h, *p_m, *p_agg, *p_stats, *p_z, *p_t, *p_dinv;
    int* p_deg;
    cudaGetSymbolAddress((void**)&p_h, g_h);
    cudaGetSymbolAddress((void**)&p_m, g_m);
    cudaGetSymbolAddress((void**)&p_agg, g_agg);
    cudaGetSymbolAddress((void**)&p_stats, g_stats);
    cudaGetSymbolAddress((void**)&p_z, g_z);
    cudaGetSymbolAddress((void**)&p_t, g_t);
    cudaGetSymbolAddress((void**)&p_dinv, g_dinv);
    cudaGetSymbolAddress((void**)&p_deg, g_deg);

    const int ND = NN * DD; // 12.8M

    // degrees + dinv
    k_zero_i<<<256, 256>>>(p_deg, NN);
    k_deg<<<(NE + 255) / 256, 256>>>(adj_row);
    k_dinv<<<(NN + 255) / 256, 256>>>();

    // h = concat(emb, x)
    k_concat<<<(ND + 255) / 256, 256>>>(emb, x);

    // ---- conv1 ----
    k_zero_f<<<2048, 256>>>(p_agg, ND);
    {
        dim3 grid(DD / 64, (NN + 63) / 64);
        k_sgemm<<<grid, 256>>>(p_h, W1, nullptr, p_m, NN, 0);
    }
    k_scatter<<<(NE + 7) / 8, 256>>>(adj_row, adj_col);
    k_combine<<<(ND + 255) / 256, 256>>>(b1, p_agg);

    // BN stats + normalize + relu
    k_zero_f<<<2, 256>>>(p_stats, 2 * DD);
    k_stats<<<(NN + 127) / 128, 256>>>();
    k_bnrelu<<<(ND + 255) / 256, 256>>>(gamma, beta);

    // ---- conv2 ----
    k_zero_f<<<2048, 256>>>(p_agg, ND);
    {
        dim3 grid(DD / 64, (NN + 63) / 64);
        k_sgemm<<<grid, 256>>>(p_h, W2, nullptr, p_m, NN, 0);
    }
    k_scatter<<<(NE + 7) / 8, 256>>>(adj_row, adj_col);
    k_combine<<<(ND + 255) / 256, 256>>>(b2, p_h);

    // ---- link predictor ----
    k_z<<<(NQ * 64 + 255) / 256, 256>>>(edges);
    {
        dim3 grid(DD / 64, (NQ + 63) / 64);
        k_sgemm<<<grid, 256>>>(p_z, pW1, pb1, p_t, NQ, 1);
    }
    k_final<<<(NQ * 32 + 255) / 256, 256>>>(pW2, pb2, out);
}

// round 2
// speedup vs baseline: 3.0675x; 3.0675x over previous
#include <cuda_runtime.h>
#include <math.h>

#define NN 50000
#define DD 256
#define NE 500000
#define NQ 200000
#define EPSV 1e-5f

// ---------------- scratch (device globals; no allocation) ----------------
__device__ float g_h[(size_t)NN * DD];     // node features / hidden
__device__ float g_m[(size_t)NN * DD];     // h @ W
__device__ float g_agg[(size_t)NN * DD];   // conv1 output (pre-BN)
__device__ float g_dinv[NN];
__device__ int   g_deg[NN];
__device__ int   g_rowptr[NN + 1];
__device__ int   g_cursor[NN];
__device__ int   g_cidx[NE];
__device__ float g_stats[2 * DD];          // [sum, sumsq] per feature

// ---------------- helpers ----------------
__device__ __forceinline__ unsigned f2tf32(float x) {
    unsigned r; asm("cvt.rna.tf32.f32 %0, %1;" : "=r"(r) : "f"(x)); return r;
}
__device__ __forceinline__ float tf32f(float x) { return __uint_as_float(f2tf32(x)); }

#define MMA_TF32(d, a, b) asm volatile( \
    "mma.sync.aligned.m16n8k8.row.col.f32.tf32.tf32.f32 " \
    "{%0,%1,%2,%3}, {%4,%5,%6,%7}, {%8,%9}, {%0,%1,%2,%3};" \
    : "+f"(d[0]), "+f"(d[1]), "+f"(d[2]), "+f"(d[3]) \
    : "r"(a[0]), "r"(a[1]), "r"(a[2]), "r"(a[3]), "r"(b[0]), "r"(b[1]))

// ---------------- utility kernels ----------------
__global__ void k_zero_f(float* __restrict__ p, int n) {
    int i = blockIdx.x * blockDim.x + threadIdx.x;
    if (i < n) p[i] = 0.f;
}
__global__ void k_zero_i(int* __restrict__ p, int n) {
    int i = blockIdx.x * blockDim.x + threadIdx.x;
    if (i < n) p[i] = 0;
}
__global__ void k_deg(const int* __restrict__ adj_row) {
    int e = blockIdx.x * blockDim.x + threadIdx.x;
    if (e < NE) atomicAdd(&g_deg[adj_row[e]], 1);
}
__global__ void k_dinv() {
    int i = blockIdx.x * blockDim.x + threadIdx.x;
    if (i < NN) g_dinv[i] = rsqrtf((float)g_deg[i] + 1.0f);
}

// exclusive scan of g_deg -> g_rowptr (and g_cursor copy). 1 block, 1024 threads.
__global__ void __launch_bounds__(1024) k_scan() {
    const int T = 1024;
    const int CH = (NN + T - 1) / T; // 49
    int tid = threadIdx.x;
    int lo = tid * CH, hi = min(lo + CH, NN);
    int s = 0;
    for (int i = lo; i < hi; i++) s += g_deg[i];
    __shared__ int sums[T];
    sums[tid] = s;
    __syncthreads();
    for (int off = 1; off < T; off <<= 1) {
        int v = (tid >= off) ? sums[tid - off] : 0;
        __syncthreads();
        sums[tid] += v;
        __syncthreads();
    }
    int run = (tid ? sums[tid - 1] : 0);
    for (int i = lo; i < hi; i++) {
        int d = g_deg[i];
        g_rowptr[i] = run;
        g_cursor[i] = run;
        run += d;
    }
    if (tid == T - 1) g_rowptr[NN] = run;
}
__global__ void k_fill(const int* __restrict__ adj_row, const int* __restrict__ adj_col) {
    int e = blockIdx.x * blockDim.x + threadIdx.x;
    if (e >= NE) return;
    int r = adj_row[e], c = adj_col[e];
    int pos = atomicAdd(&g_cursor[r], 1);
    g_cidx[pos] = c;
}

// h = concat(emb, x)
__global__ void k_concat(const float* __restrict__ emb, const float* __restrict__ x) {
    int idx = blockIdx.x * blockDim.x + threadIdx.x;
    if (idx >= NN * DD) return;
    int i = idx >> 8, j = idx & 255;
    g_h[idx] = (j < 128) ? emb[i * 128 + j] : x[i * 128 + (j - 128)];
}

// ---------------- tf32 tensor-core GEMM ----------------
// C[M,256] = A[M,256] @ B[256,256]. Block: 256 thr = 8 warps (2 M x 4 N).
// Block tile 64x256, warp tile 32x64, k-block 32, mma m16n8k8.
// MODE 0: conv (A from gmem, store C)
// MODE 1: link predictor (A = h[u]*h[v] on the fly; epilogue relu(.+pb1)@pW2+pb2 -> sigmoid)
template <int MODE>
__global__ void __launch_bounds__(256, 2) k_gemm(
    const float* __restrict__ A, const float* __restrict__ B,
    float* __restrict__ C, int M,
    const int* __restrict__ edges,
    const float* __restrict__ pb1, const float* __restrict__ pW2,
    const float* __restrict__ pb2)
{
    __shared__ __align__(16) float As[64][36];
    __shared__ __align__(16) float Bs[32][260];
    __shared__ int su[64], sv[64];
    __shared__ float w2s[256], b1s[256], rsum[64];

    const int tid = threadIdx.x;
    const int warp = tid >> 5, lane = tid & 31;
    const int warp_m = warp >> 2, warp_n = warp & 3;
    const int g = lane >> 2, t = lane & 3;
    const int m0 = blockIdx.x * 64;

    if (MODE == 1) {
        if (tid < 64) {
            su[tid] = edges[m0 + tid];
            sv[tid] = edges[NQ + m0 + tid];
            rsum[tid] = 0.f;
        }
        if (tid < 256) { w2s[tid] = pW2[tid]; b1s[tid] = pb1[tid]; }
        __syncthreads();
    }

    float acc[2][8][4];
#pragma unroll
    for (int i = 0; i < 2; i++)
#pragma unroll
        for (int j = 0; j < 8; j++)
#pragma unroll
            for (int k = 0; k < 4; k++) acc[i][j][k] = 0.f;

    for (int k0 = 0; k0 < DD; k0 += 32) {
        // ---- load A tile (64 x 32) ----
#pragma unroll
        for (int i = 0; i < 2; i++) {
            int p = tid + i * 256;           // 0..511
            int row = p >> 3, c4 = p & 7;
            float4 av = make_float4(0.f, 0.f, 0.f, 0.f);
            if (MODE == 0) {
                int gr = m0 + row;
                if (gr < M) av = *(const float4*)(A + (size_t)gr * DD + k0 + c4 * 4);
            } else {
                int u = su[row], v = sv[row];
                float4 hu = *(const float4*)(A + (size_t)u * DD + k0 + c4 * 4);
                float4 hv = *(const float4*)(A + (size_t)v * DD + k0 + c4 * 4);
                av = make_float4(hu.x * hv.x, hu.y * hv.y, hu.z * hv.z, hu.w * hv.w);
            }
            av.x = tf32f(av.x); av.y = tf32f(av.y); av.z = tf32f(av.z); av.w = tf32f(av.w);
            *(float4*)&As[row][c4 * 4] = av;
        }
        // ---- load B tile (32 x 256) ----
#pragma unroll
        for (int i = 0; i < 8; i++) {
            int q = tid + i * 256;           // 0..2047
            int row = q >> 6, c4 = q & 63;
            float4 bv = *(const float4*)(B + (size_t)(k0 + row) * DD + c4 * 4);
            bv.x = tf32f(bv.x); bv.y = tf32f(bv.y); bv.z = tf32f(bv.z); bv.w = tf32f(bv.w);
            *(float4*)&Bs[row][c4 * 4] = bv;
        }
        __syncthreads();

#pragma unroll
        for (int ks = 0; ks < 4; ks++) {
            const int kk = ks * 8;
            unsigned a[2][4], b[8][2];
#pragma unroll
            for (int mt = 0; mt < 2; mt++) {
                int ra = warp_m * 32 + mt * 16;
                a[mt][0] = __float_as_uint(As[ra + g][kk + t]);
                a[mt][1] = __float_as_uint(As[ra + 8 + g][kk + t]);
                a[mt][2] = __float_as_uint(As[ra + g][kk + t + 4]);
                a[mt][3] = __float_as_uint(As[ra + 8 + g][kk + t + 4]);
            }
#pragma unroll
            for (int nt = 0; nt < 8; nt++) {
                int cb = warp_n * 64 + nt * 8;
                b[nt][0] = __float_as_uint(Bs[kk + t][cb + g]);
                b[nt][1] = __float_as_uint(Bs[kk + t + 4][cb + g]);
            }
#pragma unroll
            for (int mt = 0; mt < 2; mt++)
#pragma unroll
                for (int nt = 0; nt < 8; nt++)
                    MMA_TF32(acc[mt][nt], a[mt], b[nt]);
        }
        __syncthreads();
    }

    if (MODE == 0) {
        // store C
#pragma unroll
        for (int mt = 0; mt < 2; mt++) {
            int r0 = m0 + warp_m * 32 + mt * 16 + g;
#pragma unroll
            for (int nt = 0; nt < 8; nt++) {
                int col = warp_n * 64 + nt * 8 + t * 2;
                if (r0 < M)
                    *(float2*)(C + (size_t)r0 * DD + col) = make_float2(acc[mt][nt][0], acc[mt][nt][1]);
                if (r0 + 8 < M)
                    *(float2*)(C + (size_t)(r0 + 8) * DD + col) = make_float2(acc[mt][nt][2], acc[mt][nt][3]);
            }
        }
    } else {
        // link epilogue: per-row dot( relu(acc + pb1), pW2 ), then sigmoid(.+pb2)
#pragma unroll
        for (int mt = 0; mt < 2; mt++) {
            float p0 = 0.f, p1 = 0.f;  // rows g and g+8 of this m-tile
#pragma unroll
            for (int nt = 0; nt < 8; nt++) {
                int col = warp_n * 64 + nt * 8 + t * 2;
                float w0 = w2s[col], w1 = w2s[col + 1];
                float bb0 = b1s[col], bb1 = b1s[col + 1];
                p0 += fmaxf(acc[mt][nt][0] + bb0, 0.f) * w0 + fmaxf(acc[mt][nt][1] + bb1, 0.f) * w1;
                p1 += fmaxf(acc[mt][nt][2] + bb0, 0.f) * w0 + fmaxf(acc[mt][nt][3] + bb1, 0.f) * w1;
            }
            int lr = warp_m * 32 + mt * 16 + g;
            atomicAdd(&rsum[lr], p0);
            atomicAdd(&rsum[lr + 8], p1);
        }
        __syncthreads();
        if (tid < 64) {
            float s = rsum[tid] + pb2[0];
            C[m0 + tid] = 1.f / (1.f + expf(-s));
        }
    }
}

// ---------------- CSR gather: out[r] = sum_c m[c]*dinv[r]dinv[c] + dinv[r]^2 m[r] + bias ----------------
__global__ void __launch_bounds__(256) k_gather(const float* __restrict__ m,
                                                const float* __restrict__ bias,
                                                float* __restrict__ out) {
    int node = blockIdx.x * 8 + (threadIdx.x >> 5);
    if (node >= NN) return;
    int lane = threadIdx.x & 31;
    float dr = g_dinv[node];
    int beg = g_rowptr[node], end = g_rowptr[node + 1];
    float4 acc0 = make_float4(0.f, 0.f, 0.f, 0.f);
    float4 acc1 = make_float4(0.f, 0.f, 0.f, 0.f);
    for (int p = beg; p < end; p++) {
        int c = g_cidx[p];
        float nrm = dr * g_dinv[c];
        const float4* src = (const float4*)(m + (size_t)c * DD);
        float4 v0 = src[lane], v1 = src[lane + 32];
        acc0.x += v0.x * nrm; acc0.y += v0.y * nrm; acc0.z += v0.z * nrm; acc0.w += v0.w * nrm;
        acc1.x += v1.x * nrm; acc1.y += v1.y * nrm; acc1.z += v1.z * nrm; acc1.w += v1.w * nrm;
    }
    float sd = dr * dr;
    const float4* ms = (const float4*)(m + (size_t)node * DD);
    float4 s0 = ms[lane], s1 = ms[lane + 32];
    float4 b0 = ((const float4*)bias)[lane], b1 = ((const float4*)bias)[lane + 32];
    acc0.x += s0.x * sd + b0.x; acc0.y += s0.y * sd + b0.y;
    acc0.z += s0.z * sd + b0.z; acc0.w += s0.w * sd + b0.w;
    acc1.x += s1.x * sd + b1.x; acc1.y += s1.y * sd + b1.y;
    acc1.z += s1.z * sd + b1.z; acc1.w += s1.w * sd + b1.w;
    float4* dst = (float4*)(out + (size_t)node * DD);
    dst[lane] = acc0; dst[lane + 32] = acc1;
}

// per-feature sum / sumsq over nodes
__global__ void __launch_bounds__(256) k_stats() {
    int j = threadIdx.x;
    int r0 = blockIdx.x * 128;
    int rend = min(r0 + 128, NN);
    float s = 0.f, sq = 0.f;
    for (int r = r0; r < rend; r++) {
        float v = g_agg[(size_t)r * DD + j];
        s += v; sq += v * v;
    }
    atomicAdd(&g_stats[j], s);
    atomicAdd(&g_stats[DD + j], sq);
}
__global__ void k_bnrelu(const float* __restrict__ gamma, const float* __restrict__ beta) {
    int idx = blockIdx.x * blockDim.x + threadIdx.x;
    if (idx >= NN * DD) return;
    int j = idx & 255;
    const float invn = 1.0f / (float)NN;
    float mean = g_stats[j] * invn;
    float var = g_stats[DD + j] * invn - mean * mean;
    float v = (g_agg[idx] - mean) * rsqrtf(var + EPSV) * gamma[j] + beta[j];
    g_h[idx] = fmaxf(v, 0.f);
}

// ---------------- launch ----------------
extern "C" void kernel_launch(void* const* d_in, const int* in_sizes, int n_in,
                              void* d_out, int out_size) {
    const float* x       = (const float*)d_in[0];
    const int*   adj_row = (const int*)d_in[1];
    const int*   adj_col = (const int*)d_in[2];
    const int*   edges   = (const int*)d_in[3];
    const float* emb     = (const float*)d_in[4];
    const float* W1      = (const float*)d_in[5];
    const float* b1      = (const float*)d_in[6];
    const float* W2      = (const float*)d_in[7];
    const float* b2      = (const float*)d_in[8];
    const float* gamma   = (const float*)d_in[9];
    const float* beta    = (const float*)d_in[10];
    const float* pW1     = (const float*)d_in[11];
    const float* pb1     = (const float*)d_in[12];
    const float* pW2     = (const float*)d_in[13];
    const float* pb2     = (const float*)d_in[14];
    float* out = (float*)d_out;

    float *p_h, *p_m, *p_agg, *p_stats;
    int* p_deg;
    cudaGetSymbolAddress((void**)&p_h, g_h);
    cudaGetSymbolAddress((void**)&p_m, g_m);
    cudaGetSymbolAddress((void**)&p_agg, g_agg);
    cudaGetSymbolAddress((void**)&p_stats, g_stats);
    cudaGetSymbolAddress((void**)&p_deg, g_deg);

    const int ND = NN * DD;

    // degrees, dinv, CSR
    k_zero_i<<<(NN + 255) / 256, 256>>>(p_deg, NN);
    k_deg<<<(NE + 255) / 256, 256>>>(adj_row);
    k_dinv<<<(NN + 255) / 256, 256>>>();
    k_scan<<<1, 1024>>>();
    k_fill<<<(NE + 255) / 256, 256>>>(adj_row, adj_col);

    // h = concat(emb, x)
    k_concat<<<(ND + 255) / 256, 256>>>(emb, x);

    // ---- conv1: m = h@W1 ; agg = gather(m)+self+b1 ----
    k_gemm<0><<<(NN + 63) / 64, 256>>>(p_h, W1, p_m, NN, nullptr, nullptr, nullptr, nullptr);
    k_gather<<<(NN + 7) / 8, 256>>>(p_m, b1, p_agg);

    // BN + ReLU -> g_h
    k_zero_f<<<2, 256>>>(p_stats, 2 * DD);
    k_stats<<<(NN + 127) / 128, 256>>>();
    k_bnrelu<<<(ND + 255) / 256, 256>>>(gamma, beta);

    // ---- conv2: m = h@W2 ; h = gather(m)+self+b2 ----
    k_gemm<0><<<(NN + 63) / 64, 256>>>(p_h, W2, p_m, NN, nullptr, nullptr, nullptr, nullptr);
    k_gather<<<(NN + 7) / 8, 256>>>(p_m, b2, p_h);

    // ---- fused link predictor: out = sigmoid(relu((h[u]*h[v])@pW1+pb1)@pW2+pb2) ----
    k_gemm<1><<<NQ / 64, 256>>>(p_h, pW1, out, NQ, edges, pb1, pW2, pb2);
}

// round 5
// speedup vs baseline: 3.5297x; 1.1507x over previous
#include <cuda_runtime.h>
#include <math.h>

#define NN 50000
#define DD 256
#define NE 500000
#define NQ 200000
#define EPSV 1e-5f
#define NB ((NN + 255) / 256)   // 196 scan blocks

// ---------------- scratch (device globals; no allocation) ----------------
__device__ float g_h[(size_t)NN * DD];     // hidden (conv2 out)
__device__ float g_m[(size_t)NN * DD];     // h @ W
__device__ float g_agg[(size_t)NN * DD];   // conv1 output (pre-BN)
__device__ float g_dinv[NN];
__device__ int   g_deg[NN];
__device__ int   g_rowptr[NN + 1];
__device__ int   g_cursor[NN];
__device__ int   g_cidx[NE];
__device__ float g_stats[2 * DD];          // [sum, sumsq]
__device__ float g_bnsc[DD], g_bnsh[DD];   // BN scale/shift
__device__ int   g_bsum[256], g_boff[256]; // scan partials

// ---------------- helpers ----------------
__device__ __forceinline__ unsigned f2tf32(float x) {
    unsigned r; asm("cvt.rna.tf32.f32 %0, %1;" : "=r"(r) : "f"(x)); return r;
}
__device__ __forceinline__ float tf32f(float x) { return __uint_as_float(f2tf32(x)); }

#define MMA_TF32(d, a, b) asm volatile( \
    "mma.sync.aligned.m16n8k8.row.col.f32.tf32.tf32.f32 " \
    "{%0,%1,%2,%3}, {%4,%5,%6,%7}, {%8,%9}, {%0,%1,%2,%3};" \
    : "+f"(d[0]), "+f"(d[1]), "+f"(d[2]), "+f"(d[3]) \
    : "r"(a[0]), "r"(a[1]), "r"(a[2]), "r"(a[3]), "r"(b[0]), "r"(b[1]))

// ---------------- small kernels ----------------
__global__ void k_zero_f(float* __restrict__ p, int n) {
    int i = blockIdx.x * blockDim.x + threadIdx.x;
    if (i < n) p[i] = 0.f;
}
__global__ void k_zero_i(int* __restrict__ p, int n) {
    int i = blockIdx.x * blockDim.x + threadIdx.x;
    if (i < n) p[i] = 0;
}
__global__ void k_deg(const int* __restrict__ adj_row) {
    int e = blockIdx.x * blockDim.x + threadIdx.x;
    if (e < NE) atomicAdd(&g_deg[adj_row[e]], 1);
}
__global__ void k_dinv() {
    int i = blockIdx.x * blockDim.x + threadIdx.x;
    if (i < NN) g_dinv[i] = rsqrtf((float)g_deg[i] + 1.0f);
}

// ---- parallel exclusive scan of g_deg (3 kernels) ----
__global__ void __launch_bounds__(256) k_degsum() {
    __shared__ int sh[256];
    int idx = blockIdx.x * 256 + threadIdx.x;
    sh[threadIdx.x] = (idx < NN) ? g_deg[idx] : 0;
    __syncthreads();
    for (int o = 128; o; o >>= 1) {
        if (threadIdx.x < o) sh[threadIdx.x] += sh[threadIdx.x + o];
        __syncthreads();
    }
    if (threadIdx.x == 0) g_bsum[blockIdx.x] = sh[0];
}
__global__ void __launch_bounds__(256) k_bscan() {
    __shared__ int sh[256];
    int tid = threadIdx.x;
    int v = (tid < NB) ? g_bsum[tid] : 0;
    sh[tid] = v;
    __syncthreads();
    for (int o = 1; o < 256; o <<= 1) {
        int t = (tid >= o) ? sh[tid - o] : 0;
        __syncthreads();
        sh[tid] += t;
        __syncthreads();
    }
    g_boff[tid] = sh[tid] - v;   // exclusive
    if (tid == 0) g_rowptr[NN] = NE;
}
__global__ void __launch_bounds__(256) k_rowptr() {
    __shared__ int sh[256];
    int tid = threadIdx.x;
    int idx = blockIdx.x * 256 + tid;
    int v = (idx < NN) ? g_deg[idx] : 0;
    sh[tid] = v;
    __syncthreads();
    for (int o = 1; o < 256; o <<= 1) {
        int t = (tid >= o) ? sh[tid - o] : 0;
        __syncthreads();
        sh[tid] += t;
        __syncthreads();
    }
    if (idx < NN) {
        int r = g_boff[blockIdx.x] + sh[tid] - v;
        g_rowptr[idx] = r;
        g_cursor[idx] = r;
    }
}
__global__ void k_fill(const int* __restrict__ adj_row, const int* __restrict__ adj_col) {
    int e = blockIdx.x * blockDim.x + threadIdx.x;
    if (e >= NE) return;
    int pos = atomicAdd(&g_cursor[adj_row[e]], 1);
    g_cidx[pos] = adj_col[e];
}

// BN per-feature scale/shift from stats
__global__ void k_bnprep(const float* __restrict__ gamma, const float* __restrict__ beta) {
    int j = threadIdx.x;
    const float invn = 1.0f / (float)NN;
    float mean = g_stats[j] * invn;
    float var = g_stats[DD + j] * invn - mean * mean;
    float rs = rsqrtf(var + EPSV) * gamma[j];
    g_bnsc[j] = rs;
    g_bnsh[j] = beta[j] - mean * rs;
}

// ---------------- tf32 tensor-core GEMM ----------------
// Block 64x256, 8 warps (2Mx4N), warp 32x64, mma m16n8k8, k-block 32.
// MODE 1: link predictor (A = h[u]*h[v]; fused relu(.+pb1)@pW2+pb2 -> sigmoid)
// MODE 2: conv1 (A = concat(emb, x) on the fly)
// MODE 3: conv2 (A = relu(bn(agg)) on the fly)
template <int MODE>
__global__ void __launch_bounds__(256, 2) k_gemm(
    const float* __restrict__ A, const float* __restrict__ B,
    float* __restrict__ C, int M,
    const float* __restrict__ X2,           // MODE 2: x
    const int* __restrict__ edges,
    const float* __restrict__ pb1, const float* __restrict__ pW2,
    const float* __restrict__ pb2)
{
    __shared__ __align__(16) float As[64][36];
    __shared__ __align__(16) float Bs[32][260];
    __shared__ int su[64], sv[64];
    __shared__ float w2s[256], b1s[256], rsum[64];
    __shared__ float bnsc[256], bnsh[256];

    const int tid = threadIdx.x;
    const int warp = tid >> 5, lane = tid & 31;
    const int warp_m = warp >> 2, warp_n = warp & 3;
    const int g = lane >> 2, t = lane & 3;
    const int m0 = blockIdx.x * 64;

    if (MODE == 1) {
        if (tid < 64) {
            su[tid] = edges[m0 + tid];
            sv[tid] = edges[NQ + m0 + tid];
            rsum[tid] = 0.f;
        }
        w2s[tid] = pW2[tid]; b1s[tid] = pb1[tid];
        __syncthreads();
    }
    if (MODE == 3) {
        bnsc[tid] = g_bnsc[tid];
        bnsh[tid] = g_bnsh[tid];
        __syncthreads();
    }

    float acc[2][8][4];
#pragma unroll
    for (int i = 0; i < 2; i++)
#pragma unroll
        for (int j = 0; j < 8; j++)
#pragma unroll
            for (int k = 0; k < 4; k++) acc[i][j][k] = 0.f;

    for (int k0 = 0; k0 < DD; k0 += 32) {
        // ---- A tile (64 x 32) ----
#pragma unroll
        for (int i = 0; i < 2; i++) {
            int p = tid + i * 256;
            int row = p >> 3, c4 = p & 7;
            int col = k0 + c4 * 4;
            float4 av = make_float4(0.f, 0.f, 0.f, 0.f);
            int gr = m0 + row;
            if (MODE == 2) {
                if (gr < M)
                    av = (col < 128) ? *(const float4*)(A + (size_t)gr * 128 + col)
                                     : *(const float4*)(X2 + (size_t)gr * 128 + (col - 128));
            } else if (MODE == 3) {
                if (gr < M) {
                    av = *(const float4*)(A + (size_t)gr * DD + col);
                    av.x = fmaxf(av.x * bnsc[col + 0] + bnsh[col + 0], 0.f);
                    av.y = fmaxf(av.y * bnsc[col + 1] + bnsh[col + 1], 0.f);
                    av.z = fmaxf(av.z * bnsc[col + 2] + bnsh[col + 2], 0.f);
                    av.w = fmaxf(av.w * bnsc[col + 3] + bnsh[col + 3], 0.f);
                }
            } else { // MODE 1
                int u = su[row], v = sv[row];
                float4 hu = *(const float4*)(A + (size_t)u * DD + col);
                float4 hv = *(const float4*)(A + (size_t)v * DD + col);
                av = make_float4(hu.x * hv.x, hu.y * hv.y, hu.z * hv.z, hu.w * hv.w);
            }
            av.x = tf32f(av.x); av.y = tf32f(av.y); av.z = tf32f(av.z); av.w = tf32f(av.w);
            *(float4*)&As[row][c4 * 4] = av;
        }
        // ---- B tile (32 x 256) ----
#pragma unroll
        for (int i = 0; i < 8; i++) {
            int q = tid + i * 256;
            int row = q >> 6, c4 = q & 63;
            float4 bv = *(const float4*)(B + (size_t)(k0 + row) * DD + c4 * 4);
            bv.x = tf32f(bv.x); bv.y = tf32f(bv.y); bv.z = tf32f(bv.z); bv.w = tf32f(bv.w);
            *(float4*)&Bs[row][c4 * 4] = bv;
        }
        __syncthreads();

#pragma unroll
        for (int ks = 0; ks < 4; ks++) {
            const int kk = ks * 8;
            unsigned a[2][4], b[8][2];
#pragma unroll
            for (int mt = 0; mt < 2; mt++) {
                int ra = warp_m * 32 + mt * 16;
                a[mt][0] = __float_as_uint(As[ra + g][kk + t]);
                a[mt][1] = __float_as_uint(As[ra + 8 + g][kk + t]);
                a[mt][2] = __float_as_uint(As[ra + g][kk + t + 4]);
                a[mt][3] = __float_as_uint(As[ra + 8 + g][kk + t + 4]);
            }
#pragma unroll
            for (int nt = 0; nt < 8; nt++) {
                int cb = warp_n * 64 + nt * 8;
                b[nt][0] = __float_as_uint(Bs[kk + t][cb + g]);
                b[nt][1] = __float_as_uint(Bs[kk + t + 4][cb + g]);
            }
#pragma unroll
            for (int mt = 0; mt < 2; mt++)
#pragma unroll
                for (int nt = 0; nt < 8; nt++)
                    MMA_TF32(acc[mt][nt], a[mt], b[nt]);
        }
        __syncthreads();
    }

    if (MODE != 1) {
#pragma unroll
        for (int mt = 0; mt < 2; mt++) {
            int r0 = m0 + warp_m * 32 + mt * 16 + g;
#pragma unroll
            for (int nt = 0; nt < 8; nt++) {
                int col = warp_n * 64 + nt * 8 + t * 2;
                if (r0 < M)
                    *(float2*)(C + (size_t)r0 * DD + col) = make_float2(acc[mt][nt][0], acc[mt][nt][1]);
                if (r0 + 8 < M)
                    *(float2*)(C + (size_t)(r0 + 8) * DD + col) = make_float2(acc[mt][nt][2], acc[mt][nt][3]);
            }
        }
    } else {
#pragma unroll
        for (int mt = 0; mt < 2; mt++) {
            float p0 = 0.f, p1 = 0.f;
#pragma unroll
            for (int nt = 0; nt < 8; nt++) {
                int col = warp_n * 64 + nt * 8 + t * 2;
                float w0 = w2s[col], w1 = w2s[col + 1];
                float bb0 = b1s[col], bb1 = b1s[col + 1];
                p0 += fmaxf(acc[mt][nt][0] + bb0, 0.f) * w0 + fmaxf(acc[mt][nt][1] + bb1, 0.f) * w1;
                p1 += fmaxf(acc[mt][nt][2] + bb0, 0.f) * w0 + fmaxf(acc[mt][nt][3] + bb1, 0.f) * w1;
            }
            int lr = warp_m * 32 + mt * 16 + g;
            atomicAdd(&rsum[lr], p0);
            atomicAdd(&rsum[lr + 8], p1);
        }
        __syncthreads();
        if (tid < 64) {
            float s = rsum[tid] + pb2[0];
            C[m0 + tid] = 1.f / (1.f + expf(-s));
        }
    }
}

// ---------------- CSR gather (+optional fused BN stats) ----------------
// grid = NN/8 exactly (6250), 8 warps/block = 8 nodes/block.
template <bool STATS>
__global__ void __launch_bounds__(256) k_gather(const float* __restrict__ m,
                                                const float* __restrict__ bias,
                                                float* __restrict__ out) {
    __shared__ float ssum[DD], ssq[DD];
    if (STATS) {
        ssum[threadIdx.x] = 0.f; ssq[threadIdx.x] = 0.f;
        __syncthreads();
    }
    int node = blockIdx.x * 8 + (threadIdx.x >> 5);
    int lane = threadIdx.x & 31;
    float dr = g_dinv[node];
    int beg = g_rowptr[node], end = g_rowptr[node + 1];
    float4 acc0 = make_float4(0.f, 0.f, 0.f, 0.f);
    float4 acc1 = make_float4(0.f, 0.f, 0.f, 0.f);
    for (int p = beg; p < end; p++) {
        int c = g_cidx[p];
        float nrm = dr * g_dinv[c];
        const float4* src = (const float4*)(m + (size_t)c * DD);
        float4 v0 = src[lane], v1 = src[lane + 32];
        acc0.x += v0.x * nrm; acc0.y += v0.y * nrm; acc0.z += v0.z * nrm; acc0.w += v0.w * nrm;
        acc1.x += v1.x * nrm; acc1.y += v1.y * nrm; acc1.z += v1.z * nrm; acc1.w += v1.w * nrm;
    }
    float sd = dr * dr;
    const float4* ms = (const float4*)(m + (size_t)node * DD);
    float4 s0 = ms[lane], s1 = ms[lane + 32];
    float4 b0 = ((const float4*)bias)[lane], b1 = ((const float4*)bias)[lane + 32];
    acc0.x += s0.x * sd + b0.x; acc0.y += s0.y * sd + b0.y;
    acc0.z += s0.z * sd + b0.z; acc0.w += s0.w * sd + b0.w;
    acc1.x += s1.x * sd + b1.x; acc1.y += s1.y * sd + b1.y;
    acc1.z += s1.z * sd + b1.z; acc1.w += s1.w * sd + b1.w;
    float4* dst = (float4*)(out + (size_t)node * DD);
    dst[lane] = acc0; dst[lane + 32] = acc1;

    if (STATS) {
        int f0 = lane * 4, f1 = 128 + lane * 4;
        atomicAdd(&ssum[f0 + 0], acc0.x); atomicAdd(&ssq[f0 + 0], acc0.x * acc0.x);
        atomicAdd(&ssum[f0 + 1], acc0.y); atomicAdd(&ssq[f0 + 1], acc0.y * acc0.y);
        atomicAdd(&ssum[f0 + 2], acc0.z); atomicAdd(&ssq[f0 + 2], acc0.z * acc0.z);
        atomicAdd(&ssum[f0 + 3], acc0.w); atomicAdd(&ssq[f0 + 3], acc0.w * acc0.w);
        atomicAdd(&ssum[f1 + 0], acc1.x); atomicAdd(&ssq[f1 + 0], acc1.x * acc1.x);
        atomicAdd(&ssum[f1 + 1], acc1.y); atomicAdd(&ssq[f1 + 1], acc1.y * acc1.y);
        atomicAdd(&ssum[f1 + 2], acc1.z); atomicAdd(&ssq[f1 + 2], acc1.z * acc1.z);
        atomicAdd(&ssum[f1 + 3], acc1.w); atomicAdd(&ssq[f1 + 3], acc1.w * acc1.w);
        __syncthreads();
        atomicAdd(&g_stats[threadIdx.x], ssum[threadIdx.x]);
        atomicAdd(&g_stats[DD + threadIdx.x], ssq[threadIdx.x]);
    }
}

// ---------------- launch ----------------
extern "C" void kernel_launch(void* const* d_in, const int* in_sizes, int n_in,
                              void* d_out, int out_size) {
    const float* x       = (const float*)d_in[0];
    const int*   adj_row = (const int*)d_in[1];
    const int*   adj_col = (const int*)d_in[2];
    const int*   edges   = (const int*)d_in[3];
    const float* emb     = (const float*)d_in[4];
    const float* W1      = (const float*)d_in[5];
    const float* b1      = (const float*)d_in[6];
    const float* W2      = (const float*)d_in[7];
    const float* b2      = (const float*)d_in[8];
    const float* gamma   = (const float*)d_in[9];
    const float* beta    = (const float*)d_in[10];
    const float* pW1     = (const float*)d_in[11];
    const float* pb1     = (const float*)d_in[12];
    const float* pW2     = (const float*)d_in[13];
    const float* pb2     = (const float*)d_in[14];
    float* out = (float*)d_out;

    float *p_h, *p_m, *p_agg, *p_stats;
    int* p_deg;
    cudaGetSymbolAddress((void**)&p_h, g_h);
    cudaGetSymbolAddress((void**)&p_m, g_m);
    cudaGetSymbolAddress((void**)&p_agg, g_agg);
    cudaGetSymbolAddress((void**)&p_stats, g_stats);
    cudaGetSymbolAddress((void**)&p_deg, g_deg);

    // degrees, dinv, CSR (parallel scan)
    k_zero_i<<<NB, 256>>>(p_deg, NN);
    k_deg<<<(NE + 255) / 256, 256>>>(adj_row);
    k_dinv<<<NB, 256>>>();
    k_degsum<<<NB, 256>>>();
    k_bscan<<<1, 256>>>();
    k_rowptr<<<NB, 256>>>();
    k_fill<<<(NE + 255) / 256, 256>>>(adj_row, adj_col);

    k_zero_f<<<2, 256>>>(p_stats, 2 * DD);

    // ---- conv1: m = concat(emb,x)@W1 ; agg = gather(m)+self+b1 (+stats) ----
    k_gemm<2><<<(NN + 63) / 64, 256>>>(emb, W1, p_m, NN, x, nullptr, nullptr, nullptr, nullptr);
    k_gather<true><<<NN / 8, 256>>>(p_m, b1, p_agg);

    // ---- conv2: m = relu(bn(agg))@W2 ; h = gather(m)+self+b2 ----
    k_bnprep<<<1, 256>>>(gamma, beta);
    k_gemm<3><<<(NN + 63) / 64, 256>>>(p_agg, W2, p_m, NN, nullptr, nullptr, nullptr, nullptr, nullptr);
    k_gather<false><<<NN / 8, 256>>>(p_m, b2, p_h);

    // ---- fused link predictor ----
    k_gemm<1><<<NQ / 64, 256>>>(p_h, pW1, out, NQ, nullptr, edges, pb1, pW2, pb2);
}